// round 15
// baseline (speedup 1.0000x reference)
#include <cuda_runtime.h>
#include <cstddef>
#include <cstdint>

#define N_LANE  20000
#define P_LANE  20
#define N_AGENT 4000
#define T_AGENT 20
#define F_DIM   8
#define H_DIM   128
#define E_LL    640000
#define E_AA    128000
#define E_LA    200000

#define AGENT_CTAS 25
#define TOTAL_CTAS 148
#define LANE_BLKS  157      // ceil(20000/128)
#define AGENT_BLKS 32       // ceil(4000/128)
#define SCAT_BLKS  1184     // 8 * 148

// ---------------- scratch (device globals; no allocation allowed) -----------
// INVARIANT: g_*_agg and g_deg_* are zero at entry to kernel_launch and are
// re-zeroed by the GNN kernels after consumption (self-restoring across the
// correctness run and every graph replay; device globals are zero-init at load).
__device__ float g_lane_enc [N_LANE  * H_DIM];
__device__ float g_agent_enc[N_AGENT * H_DIM];
__device__ float g_lane_agg [N_LANE  * H_DIM];
__device__ float g_agent_agg[N_AGENT * H_DIM];
__device__ float g_ms_l    [N_LANE  * H_DIM];
__device__ float g_ms_a    [N_AGENT * H_DIM];
__device__ float g_deg_l[N_LANE];
__device__ float g_deg_a[N_AGENT];

// ---------------- PTX helpers -------------------------------------------------
__device__ __forceinline__ uint32_t smem_u32(const void* p) {
    uint32_t a;
    asm("{ .reg .u64 t; cvta.to.shared.u64 t, %1; cvt.u32.u64 %0, t; }" : "=r"(a) : "l"(p));
    return a;
}
__device__ __forceinline__ void cp_async16(float* dst, const float* src) {
    asm volatile("cp.async.cg.shared.global [%0], [%1], 16;"
                 :: "r"(smem_u32(dst)), "l"(src));
}
#define CP_COMMIT() asm volatile("cp.async.commit_group;" ::: "memory")
#define CP_WAIT0()  asm volatile("cp.async.wait_group 0;" ::: "memory")

__device__ __forceinline__ uint32_t f2tf32(float f) {
    uint32_t u;
    asm("cvt.rna.tf32.f32 %0, %1;" : "=r"(u) : "f"(f));
    return u;
}
__device__ __forceinline__ void mma_tf32(float c[4], const uint32_t a[4],
                                         uint32_t b0, uint32_t b1) {
    asm("mma.sync.aligned.m16n8k8.row.col.f32.tf32.tf32.f32 "
        "{%0,%1,%2,%3}, {%4,%5,%6,%7}, {%8,%9}, {%0,%1,%2,%3};"
        : "+f"(c[0]), "+f"(c[1]), "+f"(c[2]), "+f"(c[3])
        : "r"(a[0]), "r"(a[1]), "r"(a[2]), "r"(a[3]), "r"(b0), "r"(b1));
}
__device__ __forceinline__ void red_add_v4(float4* a, float4 v) {
    asm volatile("red.global.add.v4.f32 [%0], {%1,%2,%3,%4};"
                 :: "l"(a), "f"(v.x), "f"(v.y), "f"(v.z), "f"(v.w) : "memory");
}

#define SA 132

// ---------------- shared Bperm init -------------------------------------------
// COALESCED: iterate linearly over w (consecutive threads read consecutive n),
// scatter into the fragment-permuted smem layout. Inverse of the old mapping:
//   l = (n&7)*4 + (k&3); re = ((n>>3)&3)*2 + ((k>>2)&1)
//   dest = (ng*16 + kc)*256 + (re>>2)*128 + l*4 + (re&3)
__device__ __forceinline__ void load_Bperm(uint32_t* Bpu, const float* __restrict__ w,
                                           int tid, int nthreads) {
    for (int idx = tid; idx < 16384; idx += nthreads) {
        const int k = idx >> 7;
        const int n = idx & 127;
        const int kc = k >> 3, ng = n >> 5;
        const int l  = (n & 7) * 4 + (k & 3);
        const int re = ((n >> 3) & 3) * 2 + ((k >> 2) & 1);
        const int dest = ((ng * 16 + kc) << 8) + ((re >> 2) << 7) + (l << 2) + (re & 3);
        Bpu[dest] = f2tf32(w[idx]);
    }
}
// single-kc variant for the K=8 stage-1 weight (4 n-groups x 256 u32)
__device__ __forceinline__ void load_Bperm8(uint32_t* Bpu, const float* __restrict__ w,
                                            int tid, int nthreads) {
    for (int idx = tid; idx < 1024; idx += nthreads) {
        const int k = idx >> 7;          // 0..7
        const int n = idx & 127;
        const int ng = n >> 5;
        const int l  = (n & 7) * 4 + (k & 3);
        const int re = ((n >> 3) & 3) * 2 + (k >> 2);
        const int dest = (ng << 8) + ((re >> 2) << 7) + (l << 2) + (re & 3);
        Bpu[dest] = f2tf32(w[idx]);
    }
}

// ---------------- shared 16-kc double-buffered mma pass ----------------------
__device__ __forceinline__ void mma_tile_16kc(float cfr[2][4][4],
                                              const uint32_t* __restrict__ Au,
                                              const uint32_t* __restrict__ Bpu,
                                              int rm, int warp_n, int lane,
                                              int tg, int tq) {
    uint32_t abuf[2][2][4];
    uint32_t bbuf[2][8];

    auto load_frags = [&](int kc, int s) {
        const int k0 = kc * 8;
#pragma unroll
        for (int mt = 0; mt < 2; mt++) {
            const int rr = rm + mt * 16;
            abuf[s][mt][0] = Au[(rr + tg) * SA + k0 + tq];
            abuf[s][mt][1] = Au[(rr + tg + 8) * SA + k0 + tq];
            abuf[s][mt][2] = Au[(rr + tg) * SA + k0 + tq + 4];
            abuf[s][mt][3] = Au[(rr + tg + 8) * SA + k0 + tq + 4];
        }
        const uint32_t base = (uint32_t)((warp_n * 16 + kc) << 8);
        const uint4 q0 = *(const uint4*)(Bpu + base + (lane << 2));
        const uint4 q1 = *(const uint4*)(Bpu + base + 128 + (lane << 2));
        bbuf[s][0] = q0.x; bbuf[s][1] = q0.y; bbuf[s][2] = q0.z; bbuf[s][3] = q0.w;
        bbuf[s][4] = q1.x; bbuf[s][5] = q1.y; bbuf[s][6] = q1.z; bbuf[s][7] = q1.w;
    };

    load_frags(0, 0);
#pragma unroll
    for (int kc = 0; kc < 16; kc++) {
        const int cur = kc & 1, nxt = cur ^ 1;
        if (kc < 15) load_frags(kc + 1, nxt);
#pragma unroll
        for (int nt = 0; nt < 4; nt++) {
            mma_tf32(cfr[0][nt], abuf[cur][0], bbuf[cur][nt * 2], bbuf[cur][nt * 2 + 1]);
            mma_tf32(cfr[1][nt], abuf[cur][1], bbuf[cur][nt * 2], bbuf[cur][nt * 2 + 1]);
        }
    }
}

// ---------------- fused tensor encoder (lane + agent), 512 threads -----------
#define ENC_TILE_NODES 6
#define ENC5_SMEM_FLOATS (16896 + 16384 + 1024 + 1920 + 128 + 128)
#define ENC5_SMEM_BYTES  (ENC5_SMEM_FLOATS * 4)

__global__ void __launch_bounds__(512, 1)
enc_both_kernel(const float* __restrict__ lane_x,
                const float* __restrict__ lw1, const float* __restrict__ lb1,
                const float* __restrict__ lw2, const float* __restrict__ lb2,
                const float* __restrict__ ax,
                const float* __restrict__ aw1, const float* __restrict__ ab1,
                const float* __restrict__ aw2, const float* __restrict__ ab2,
                float* __restrict__ ms_l, float* __restrict__ ms_a)
{
    extern __shared__ float smem[];
    float* A     = smem;               // tf32 x' -> tf32 h -> f32 Dbuf
    float* Bperm = A + 16896;          // w2 permuted (16 kc)
    float* Bp1   = Bperm + 16384;      // w1 permuted (1 kc)
    float* xs    = Bp1 + 1024;         // 2 x 960
    float* b1s   = xs + 1920;
    float* b2s   = b1s + 128;

    uint32_t* Au   = (uint32_t*)A;
    uint32_t* Bpu  = (uint32_t*)Bperm;
    uint32_t* Bp1u = (uint32_t*)Bp1;

    const bool is_agent = blockIdx.x < AGENT_CTAS;
    const float* x_in = is_agent ? ax  : lane_x;
    const float* w1   = is_agent ? aw1 : lw1;
    const float* b1   = is_agent ? ab1 : lb1;
    const float* w2   = is_agent ? aw2 : lw2;
    const float* b2   = is_agent ? ab2 : lb2;
    float* ms_out     = is_agent ? ms_a : ms_l;
    const int n_nodes = is_agent ? N_AGENT : N_LANE;
    const int n_tiles = (n_nodes + ENC_TILE_NODES - 1) / ENC_TILE_NODES;
    const int cta0    = is_agent ? blockIdx.x : blockIdx.x - AGENT_CTAS;
    const int ncta    = is_agent ? AGENT_CTAS : TOTAL_CTAS - AGENT_CTAS;

    const int tid  = threadIdx.x;      // 0..511
    const int wid  = tid >> 5;         // 0..15
    const int lane = tid & 31;
    const int tg = lane >> 2;
    const int tq = lane & 3;
    const int warp_m = wid & 3;
    const int warp_n = wid >> 2;
    const int rm = warp_m * 32;

    load_Bperm(Bpu, w2, tid, 512);
    load_Bperm8(Bp1u, w1, tid, 512);
    if (tid < H_DIM) { b1s[tid] = b1[tid]; b2s[tid] = b2[tid]; }

    auto prefetch = [&](int tile, int buf) {
        const int node0 = tile * ENC_TILE_NODES;
        for (int i = tid; i < 240; i += 512) {
            int j = i / 40;
            int nd = node0 + j; if (nd >= n_nodes) nd = n_nodes - 1;
            cp_async16(xs + buf * 960 + i * 4,
                       x_in + (size_t)nd * 160 + (i - j * 40) * 4);
        }
    };

    int buf = 0;
    if (cta0 < n_tiles) { prefetch(cta0, 0); }
    CP_COMMIT();
    __syncthreads();                   // Bperm/Bp1/biases visible

    for (int tile = cta0; tile < n_tiles; tile += ncta) {
        const int node0 = tile * ENC_TILE_NODES;

        CP_WAIT0();
        __syncthreads();
        const float* xc = xs + buf * 960;

        {
            int ntile = tile + ncta;
            if (ntile < n_tiles) prefetch(ntile, buf ^ 1);
            CP_COMMIT();
        }

        // ---- build A = tf32(x') [120 rows x 8 k], ref-subtract folded ----
        for (int idx = tid; idx < 960; idx += 512) {
            const int r = idx >> 3, k = idx & 7;
            const int j = r / 20;
            const int t = r - j * 20;
            float val = xc[j * 160 + t * 8 + k];
            if (k < 2) val -= xc[j * 160 + 152 + k];
            Au[r * SA + k] = f2tf32(val);
        }
        __syncthreads();

        // ---- stage 1 mma: pre1 = x' @ w1 (single kc-step) ----
        float cfr[2][4][4];
#pragma unroll
        for (int mt = 0; mt < 2; mt++)
#pragma unroll
            for (int nt = 0; nt < 4; nt++)
#pragma unroll
                for (int q = 0; q < 4; q++) cfr[mt][nt][q] = 0.f;
        {
            uint32_t afr[2][4];
#pragma unroll
            for (int mt = 0; mt < 2; mt++) {
                const int rr = rm + mt * 16;
                afr[mt][0] = Au[(rr + tg) * SA + tq];
                afr[mt][1] = Au[(rr + tg + 8) * SA + tq];
                afr[mt][2] = Au[(rr + tg) * SA + tq + 4];
                afr[mt][3] = Au[(rr + tg + 8) * SA + tq + 4];
            }
            const uint32_t base = (uint32_t)(warp_n << 8);
            const uint4 q0 = *(const uint4*)(Bp1u + base + (lane << 2));
            const uint4 q1 = *(const uint4*)(Bp1u + base + 128 + (lane << 2));
#pragma unroll
            for (int mt = 0; mt < 2; mt++) {
                mma_tf32(cfr[mt][0], afr[mt], q0.x, q0.y);
                mma_tf32(cfr[mt][1], afr[mt], q0.z, q0.w);
                mma_tf32(cfr[mt][2], afr[mt], q1.x, q1.y);
                mma_tf32(cfr[mt][3], afr[mt], q1.z, q1.w);
            }
        }
        __syncthreads();   // all stage-1 A reads done before h overwrites A

        // ---- h = tf32(relu(pre1 + b1)) -> A ----
#pragma unroll
        for (int mt = 0; mt < 2; mt++) {
            const int rr = rm + mt * 16 + tg;
#pragma unroll
            for (int nt = 0; nt < 4; nt++) {
                const int cc = warp_n * 32 + nt * 8 + 2 * tq;
                Au[rr * SA + cc]     = f2tf32(fmaxf(cfr[mt][nt][0] + b1s[cc], 0.f));
                Au[rr * SA + cc + 1] = f2tf32(fmaxf(cfr[mt][nt][1] + b1s[cc + 1], 0.f));
                Au[(rr + 8) * SA + cc]     = f2tf32(fmaxf(cfr[mt][nt][2] + b1s[cc], 0.f));
                Au[(rr + 8) * SA + cc + 1] = f2tf32(fmaxf(cfr[mt][nt][3] + b1s[cc + 1], 0.f));
            }
        }
        __syncthreads();

        // ---- stage 2 mma: D = h @ w2 ----
#pragma unroll
        for (int mt = 0; mt < 2; mt++)
#pragma unroll
            for (int nt = 0; nt < 4; nt++)
#pragma unroll
                for (int q = 0; q < 4; q++) cfr[mt][nt][q] = 0.f;

        mma_tile_16kc(cfr, Au, Bpu, rm, warp_n, lane, tg, tq);
        __syncthreads();   // all A reads done; A memory becomes Dbuf

        // ---- store C frags to Dbuf (skip unused rows >= 120) ----
#pragma unroll
        for (int mt = 0; mt < 2; mt++) {
            const int rr = rm + mt * 16 + tg;
#pragma unroll
            for (int nt = 0; nt < 4; nt++) {
                const int cc = warp_n * 32 + nt * 8 + 2 * tq;
                if (rr < 120)
                    *(float2*)(A + rr * SA + cc) =
                        make_float2(cfr[mt][nt][0], cfr[mt][nt][1]);
                if (rr + 8 < 120)
                    *(float2*)(A + (rr + 8) * SA + cc) =
                        make_float2(cfr[mt][nt][2], cfr[mt][nt][3]);
            }
        }
        __syncthreads();

        // ---- per-node max + bias + relu -> ms ----
        for (int task = tid; task < ENC_TILE_NODES * H_DIM; task += 512) {
            const int j = task >> 7, cc = task & 127;
            const int nd = node0 + j;
            if (nd < n_nodes) {
                float m = -3.4e38f;
                const float* dp = A + (j * 20) * SA + cc;
#pragma unroll
                for (int r = 0; r < 20; r++) m = fmaxf(m, dp[r * SA]);
                ms_out[(size_t)nd * H_DIM + cc] = fmaxf(m + b2s[cc], 0.f);
            }
        }
        __syncthreads();
        buf ^= 1;
    }
}

// ---------------- fused tensor MLP (lane + agent) ----------------------------
#define MLP2_SMEM_FLOATS (16896 + 16384 + 128)
#define MLP2_SMEM_BYTES  (MLP2_SMEM_FLOATS * 4)

__global__ void __launch_bounds__(512, 1)
mlp_both_kernel(const float* __restrict__ inL, const float* __restrict__ wL,
                const float* __restrict__ bL, float* __restrict__ outL,
                const float* __restrict__ inA, const float* __restrict__ wA,
                const float* __restrict__ bA, float* __restrict__ outA)
{
    extern __shared__ float smem[];
    float* A     = smem;
    float* Bperm = A + 16896;
    float* bs    = Bperm + 16384;
    uint32_t* Au  = (uint32_t*)A;
    uint32_t* Bpu = (uint32_t*)Bperm;

    const bool is_agent = blockIdx.x >= LANE_BLKS;
    const float* in_feat = is_agent ? inA : inL;
    const float* w       = is_agent ? wA : wL;
    const float* b       = is_agent ? bA : bL;
    float* out           = is_agent ? outA : outL;
    const int n_nodes    = is_agent ? N_AGENT : N_LANE;
    const int n0 = (is_agent ? (blockIdx.x - LANE_BLKS) : blockIdx.x) * 128;

    const int tid  = threadIdx.x;
    const int wid  = tid >> 5;
    const int lane = tid & 31;
    const int tg = lane >> 2;
    const int tq = lane & 3;
    const int warp_m = wid & 3;
    const int warp_n = wid >> 2;
    const int rm = warp_m * 32;

    load_Bperm(Bpu, w, tid, 512);
    if (tid < H_DIM) bs[tid] = b[tid];

    {
        const int c  = tid & 127;
        const int r0 = (tid >> 7) * 32;
        for (int i = 0; i < 32; i++) {
            int r = r0 + i;
            int idx = n0 + r; if (idx >= n_nodes) idx = n_nodes - 1;
            Au[r * SA + c] = f2tf32(in_feat[(size_t)idx * H_DIM + c]);
        }
    }
    __syncthreads();

    float cfr[2][4][4];
#pragma unroll
    for (int mt = 0; mt < 2; mt++)
#pragma unroll
        for (int nt = 0; nt < 4; nt++)
#pragma unroll
            for (int q = 0; q < 4; q++) cfr[mt][nt][q] = 0.f;

    mma_tile_16kc(cfr, Au, Bpu, rm, warp_n, lane, tg, tq);

#pragma unroll
    for (int mt = 0; mt < 2; mt++) {
        const int rr = rm + mt * 16 + tg;
#pragma unroll
        for (int nt = 0; nt < 4; nt++) {
            const int cc = warp_n * 32 + nt * 8 + 2 * tq;
            const float2 bv = make_float2(bs[cc], bs[cc + 1]);
            const int nd0 = n0 + rr;
            if (nd0 < n_nodes)
                *(float2*)(out + (size_t)nd0 * H_DIM + cc) =
                    make_float2(fmaxf(cfr[mt][nt][0] + bv.x, 0.f),
                                fmaxf(cfr[mt][nt][1] + bv.y, 0.f));
            const int nd1 = nd0 + 8;
            if (nd1 < n_nodes)
                *(float2*)(out + (size_t)nd1 * H_DIM + cc) =
                    make_float2(fmaxf(cfr[mt][nt][2] + bv.x, 0.f),
                                fmaxf(cfr[mt][nt][3] + bv.y, 0.f));
        }
    }
}

// ---------------- fused tensor GNN (all passes zero agg/deg after reading) ---
#define GNN2_SMEM_FLOATS (16896 + 16384 + 128 + 128)
#define GNN2_SMEM_BYTES  (GNN2_SMEM_FLOATS * 4)

__device__ __forceinline__ void gnn_body(
    const float* __restrict__ node_in, float* __restrict__ agg,
    float* __restrict__ deg,
    const float* __restrict__ w1, const float* __restrict__ b1,
    const float* __restrict__ w2, const float* __restrict__ b2,
    float* __restrict__ out, int n_nodes, int n0)
{
    extern __shared__ float smem[];
    float* A     = smem;
    float* Bperm = A + 16896;
    float* bs1   = Bperm + 16384;
    float* bs2   = bs1 + 128;
    uint32_t* Au  = (uint32_t*)A;
    uint32_t* Bpu = (uint32_t*)Bperm;

    const int tid  = threadIdx.x;
    const int wid  = tid >> 5;
    const int lane = tid & 31;
    const int tg = lane >> 2;
    const int tq = lane & 3;
    const int warp_m = wid & 3;
    const int warp_n = wid >> 2;
    const int rm = warp_m * 32;

    const int c  = tid & 127;
    const int r0 = (tid >> 7) * 32;

    // phase 0: Bp = w1[0:128], A = node rows
    load_Bperm(Bpu, w1, tid, 512);
    if (tid < H_DIM) { bs1[tid] = b1[tid]; bs2[tid] = b2[tid]; }
    for (int i = 0; i < 32; i++) {
        int r = r0 + i;
        int idx = n0 + r; if (idx >= n_nodes) idx = n_nodes - 1;
        Au[r * SA + c] = f2tf32(node_in[(size_t)idx * H_DIM + c]);
    }
    __syncthreads();

    float cfr[2][4][4];
#pragma unroll
    for (int mt = 0; mt < 2; mt++)
#pragma unroll
        for (int nt = 0; nt < 4; nt++)
#pragma unroll
            for (int q = 0; q < 4; q++) cfr[mt][nt][q] = 0.f;

    mma_tile_16kc(cfr, Au, Bpu, rm, warp_n, lane, tg, tq);
    __syncthreads();

    // phase 2: Bp = w1[128:256], A = agg/deg, agg zeroed after read
    // (per-thread-private). deg zeroing deferred past the sync below
    // (128 threads read each deg entry).
    load_Bperm(Bpu, w1 + 128 * H_DIM, tid, 512);
    for (int i = 0; i < 32; i++) {
        int r = r0 + i;
        int idx = n0 + r;
        bool valid = idx < n_nodes;
        if (!valid) idx = n_nodes - 1;
        const float dv = deg[idx];
        const float invd = 1.0f / fmaxf(dv, 1.0f);
        const float av = agg[(size_t)idx * H_DIM + c];
        Au[r * SA + c] = f2tf32(av * invd);
        if (valid)
            agg[(size_t)idx * H_DIM + c] = 0.f;
    }
    __syncthreads();
    if (c == 0) {
        for (int i = 0; i < 32; i++) {
            int idx = n0 + r0 + i;
            if (idx < n_nodes) deg[idx] = 0.f;
        }
    }

    mma_tile_16kc(cfr, Au, Bpu, rm, warp_n, lane, tg, tq);
    __syncthreads();

    // phase 4: h = relu(cfr + b1) -> A (tf32); Bp = w2
#pragma unroll
    for (int mt = 0; mt < 2; mt++) {
        const int rr = rm + mt * 16 + tg;
#pragma unroll
        for (int nt = 0; nt < 4; nt++) {
            const int cc = warp_n * 32 + nt * 8 + 2 * tq;
            Au[rr * SA + cc]     = f2tf32(fmaxf(cfr[mt][nt][0] + bs1[cc], 0.f));
            Au[rr * SA + cc + 1] = f2tf32(fmaxf(cfr[mt][nt][1] + bs1[cc + 1], 0.f));
            Au[(rr + 8) * SA + cc]     = f2tf32(fmaxf(cfr[mt][nt][2] + bs1[cc], 0.f));
            Au[(rr + 8) * SA + cc + 1] = f2tf32(fmaxf(cfr[mt][nt][3] + bs1[cc + 1], 0.f));
        }
    }
    load_Bperm(Bpu, w2, tid, 512);
    __syncthreads();

    // phase 6: layer 2 mma
#pragma unroll
    for (int mt = 0; mt < 2; mt++)
#pragma unroll
        for (int nt = 0; nt < 4; nt++)
#pragma unroll
            for (int q = 0; q < 4; q++) cfr[mt][nt][q] = 0.f;

    mma_tile_16kc(cfr, Au, Bpu, rm, warp_n, lane, tg, tq);

    // epilogue: out = node + relu(cfr + b2)
#pragma unroll
    for (int mt = 0; mt < 2; mt++) {
        const int rr = rm + mt * 16 + tg;
#pragma unroll
        for (int nt = 0; nt < 4; nt++) {
            const int cc = warp_n * 32 + nt * 8 + 2 * tq;
            const float2 bv = make_float2(bs2[cc], bs2[cc + 1]);
            const int nd0 = n0 + rr;
            if (nd0 < n_nodes) {
                const float2 nv = *(const float2*)(node_in + (size_t)nd0 * H_DIM + cc);
                *(float2*)(out + (size_t)nd0 * H_DIM + cc) =
                    make_float2(nv.x + fmaxf(cfr[mt][nt][0] + bv.x, 0.f),
                                nv.y + fmaxf(cfr[mt][nt][1] + bv.y, 0.f));
            }
            const int nd1 = nd0 + 8;
            if (nd1 < n_nodes) {
                const float2 nv = *(const float2*)(node_in + (size_t)nd1 * H_DIM + cc);
                *(float2*)(out + (size_t)nd1 * H_DIM + cc) =
                    make_float2(nv.x + fmaxf(cfr[mt][nt][2] + bv.x, 0.f),
                                nv.y + fmaxf(cfr[mt][nt][3] + bv.y, 0.f));
            }
        }
    }
}

__global__ void __launch_bounds__(512, 1)
gnn_both_kernel(const float* __restrict__ lane_in, float* __restrict__ lane_agg,
                float* __restrict__ deg_l,
                const float* __restrict__ ll_w1, const float* __restrict__ ll_b1,
                const float* __restrict__ ll_w2, const float* __restrict__ ll_b2,
                float* __restrict__ lane_out,
                const float* __restrict__ agent_in, float* __restrict__ agent_agg,
                float* __restrict__ deg_a,
                const float* __restrict__ aa_w1, const float* __restrict__ aa_b1,
                const float* __restrict__ aa_w2, const float* __restrict__ aa_b2,
                float* __restrict__ agent_out)
{
    if (blockIdx.x < LANE_BLKS) {
        gnn_body(lane_in, lane_agg, deg_l, ll_w1, ll_b1, ll_w2, ll_b2,
                 lane_out, N_LANE, blockIdx.x * 128);
    } else {
        gnn_body(agent_in, agent_agg, deg_a, aa_w1, aa_b1, aa_w2, aa_b2,
                 agent_out, N_AGENT, (blockIdx.x - LANE_BLKS) * 128);
    }
}

__global__ void __launch_bounds__(512, 1)
gnn_la_kernel(const float* __restrict__ node_in, float* __restrict__ agg,
              float* __restrict__ deg,
              const float* __restrict__ w1, const float* __restrict__ b1,
              const float* __restrict__ w2, const float* __restrict__ b2,
              float* __restrict__ out)
{
    gnn_body(node_in, agg, deg, w1, b1, w2, b2, out, N_AGENT,
             blockIdx.x * 128);
}

// ---------------- fused edge scatter (LL + AA), grid-stride + idx prefetch ---
__global__ void scatter_both_kernel(const int* __restrict__ e_ll,
                                    const int* __restrict__ e_aa,
                                    const float* __restrict__ lane_feat,
                                    float* __restrict__ lane_agg,
                                    float* __restrict__ deg_l,
                                    const float* __restrict__ agent_feat,
                                    float* __restrict__ agent_agg,
                                    float* __restrict__ deg_a)
{
    const int nwarps = (gridDim.x * blockDim.x) >> 5;
    const int lane = threadIdx.x & 31;
    int e = (blockIdx.x * blockDim.x + threadIdx.x) >> 5;
    const int total = E_LL + E_AA;
    if (e >= total) return;

    auto load_idx = [&](int ei, int& s, int& d) {
        if (ei < E_LL) { s = e_ll[ei]; d = e_ll[E_LL + ei]; }
        else           { s = e_aa[ei - E_LL]; d = e_aa[E_AA + ei - E_LL]; }
    };

    int s, d;
    load_idx(e, s, d);
    while (e < total) {
        const int en = e + nwarps;
        int s2 = 0, d2 = 0;
        if (en < total) load_idx(en, s2, d2);

        const bool is_ll = e < E_LL;
        const float* feat = is_ll ? lane_feat : agent_feat;
        float* agg = is_ll ? lane_agg : agent_agg;
        float* deg = is_ll ? deg_l : deg_a;

        const float4 v = ((const float4*)(feat + (size_t)s * H_DIM))[lane];
        red_add_v4(((float4*)(agg + (size_t)d * H_DIM)) + lane, v);
        if (lane == 0) atomicAdd(deg + d, 1.0f);

        e = en; s = s2; d = d2;
    }
}

__global__ void scatter_la_kernel(const int* __restrict__ e_la,
                                  const float* __restrict__ feat,
                                  float* __restrict__ agg,
                                  float* __restrict__ deg)
{
    const int nwarps = (gridDim.x * blockDim.x) >> 5;
    const int lane = threadIdx.x & 31;
    int e = (blockIdx.x * blockDim.x + threadIdx.x) >> 5;
    if (e >= E_LA) return;

    int s = e_la[e], d = e_la[E_LA + e];
    while (e < E_LA) {
        const int en = e + nwarps;
        int s2 = 0, d2 = 0;
        if (en < E_LA) { s2 = e_la[en]; d2 = e_la[E_LA + en]; }

        const float4 v = ((const float4*)(feat + (size_t)s * H_DIM))[lane];
        red_add_v4(((float4*)(agg + (size_t)d * H_DIM)) + lane, v);
        if (lane == 0) atomicAdd(deg + d, 1.0f);

        e = en; s = s2; d = d2;
    }
}

// ---------------- launch -----------------------------------------------------
extern "C" void kernel_launch(void* const* d_in, const int* in_sizes, int n_in,
                              void* d_out, int out_size)
{
    const float* lane_points   = (const float*)d_in[0];
    const float* agent_history = (const float*)d_in[1];
    const int* e_ll = (const int*)d_in[2];
    const int* e_aa = (const int*)d_in[3];
    const int* e_la = (const int*)d_in[4];
    const float* lw1 = (const float*)d_in[5];
    const float* lb1 = (const float*)d_in[6];
    const float* lw2 = (const float*)d_in[7];
    const float* lb2 = (const float*)d_in[8];
    const float* lw3 = (const float*)d_in[9];
    const float* lb3 = (const float*)d_in[10];
    const float* aw1 = (const float*)d_in[11];
    const float* ab1 = (const float*)d_in[12];
    const float* aw2 = (const float*)d_in[13];
    const float* ab2 = (const float*)d_in[14];
    const float* aw3 = (const float*)d_in[15];
    const float* ab3 = (const float*)d_in[16];
    const float* ll_w1 = (const float*)d_in[17];
    const float* ll_b1 = (const float*)d_in[18];
    const float* ll_w2 = (const float*)d_in[19];
    const float* ll_b2 = (const float*)d_in[20];
    const float* aa_w1 = (const float*)d_in[21];
    const float* aa_b1 = (const float*)d_in[22];
    const float* aa_w2 = (const float*)d_in[23];
    const float* aa_b2 = (const float*)d_in[24];
    const float* la_w1 = (const float*)d_in[25];
    const float* la_b1 = (const float*)d_in[26];
    const float* la_w2 = (const float*)d_in[27];
    const float* la_b2 = (const float*)d_in[28];

    float* out = (float*)d_out;
    float* lane_out  = out;
    float* agent_out = out + (size_t)N_LANE * H_DIM;

    float *p_lane_enc, *p_agent_enc, *p_lane_agg, *p_agent_agg;
    float *p_ms_l, *p_ms_a, *p_deg_l, *p_deg_a;
    cudaGetSymbolAddress((void**)&p_lane_enc,  g_lane_enc);
    cudaGetSymbolAddress((void**)&p_agent_enc, g_agent_enc);
    cudaGetSymbolAddress((void**)&p_lane_agg,  g_lane_agg);
    cudaGetSymbolAddress((void**)&p_agent_agg, g_agent_agg);
    cudaGetSymbolAddress((void**)&p_ms_l,      g_ms_l);
    cudaGetSymbolAddress((void**)&p_ms_a,      g_ms_a);
    cudaGetSymbolAddress((void**)&p_deg_l,     g_deg_l);
    cudaGetSymbolAddress((void**)&p_deg_a,     g_deg_a);

    cudaFuncSetAttribute(enc_both_kernel, cudaFuncAttributeMaxDynamicSharedMemorySize, ENC5_SMEM_BYTES);
    cudaFuncSetAttribute(mlp_both_kernel, cudaFuncAttributeMaxDynamicSharedMemorySize, MLP2_SMEM_BYTES);
    cudaFuncSetAttribute(gnn_both_kernel, cudaFuncAttributeMaxDynamicSharedMemorySize, GNN2_SMEM_BYTES);
    cudaFuncSetAttribute(gnn_la_kernel,   cudaFuncAttributeMaxDynamicSharedMemorySize, GNN2_SMEM_BYTES);

    // NOTE: no zero kernel — agg/deg buffers are zero-init device globals and
    // each GNN pass re-zeroes what it consumed (invariant holds every call).

    // 1. fused encoders (agent CTAs 0..24, lane CTAs 25..147)
    enc_both_kernel<<<TOTAL_CTAS, 512, ENC5_SMEM_BYTES>>>(
        lane_points, lw1, lb1, lw2, lb2,
        agent_history, aw1, ab1, aw2, ab2, p_ms_l, p_ms_a);

    // 2. fused stage-3 MLPs
    mlp_both_kernel<<<LANE_BLKS + AGENT_BLKS, 512, MLP2_SMEM_BYTES>>>(
        p_ms_l, lw3, lb3, p_lane_enc,
        p_ms_a, aw3, ab3, p_agent_enc);

    // 3. fused LL + AA scatter (grid-stride, index-prefetch)
    scatter_both_kernel<<<SCAT_BLKS, 256>>>(
        e_ll, e_aa, p_lane_enc, p_lane_agg, p_deg_l,
        p_agent_enc, p_agent_agg, p_deg_a);

    // 4. fused LL + AA GNN (both halves zero their agg/deg after reading)
    gnn_both_kernel<<<LANE_BLKS + AGENT_BLKS, 512, GNN2_SMEM_BYTES>>>(
        p_lane_enc, p_lane_agg, p_deg_l, ll_w1, ll_b1, ll_w2, ll_b2, lane_out,
        p_agent_enc, p_agent_agg, p_deg_a, aa_w1, aa_b1, aa_w2, aa_b2, agent_out);

    // 5. LA scatter (source = updated lane; agent agg/deg zeroed by step 4)
    scatter_la_kernel<<<SCAT_BLKS, 256>>>(e_la, lane_out, p_agent_agg, p_deg_a);

    // 6. LA GNN (in-place on agent_out; zeroes agent agg/deg for next call)
    gnn_la_kernel<<<AGENT_BLKS, 512, GNN2_SMEM_BYTES>>>(
        agent_out, p_agent_agg, p_deg_a, la_w1, la_b1, la_w2, la_b2, agent_out);
}

// round 17
// speedup vs baseline: 1.1362x; 1.1362x over previous
#include <cuda_runtime.h>
#include <cstddef>
#include <cstdint>

#define N_LANE  20000
#define P_LANE  20
#define N_AGENT 4000
#define T_AGENT 20
#define F_DIM   8
#define H_DIM   128
#define E_LL    640000
#define E_AA    128000
#define E_LA    200000

#define AGENT_CTAS 25
#define TOTAL_CTAS 148
#define LANE_BLKS  157      // ceil(20000/128)
#define AGENT_BLKS 32       // ceil(4000/128)
#define SCAT_BLKS  1184     // 8 * 148

// ---------------- scratch (device globals; no allocation allowed) -----------
// INVARIANT: g_*_agg and g_deg_* are zero at entry to kernel_launch and are
// re-zeroed by the GNN kernels after consumption (self-restoring across the
// correctness run and every graph replay; device globals are zero-init at load).
__device__ float g_lane_enc [N_LANE  * H_DIM];
__device__ float g_agent_enc[N_AGENT * H_DIM];
__device__ float g_lane_agg [N_LANE  * H_DIM];
__device__ float g_agent_agg[N_AGENT * H_DIM];
__device__ float g_ms_l    [N_LANE  * H_DIM];
__device__ float g_ms_a    [N_AGENT * H_DIM];
__device__ float g_deg_l[N_LANE];
__device__ float g_deg_a[N_AGENT];

// ---------------- PTX helpers -------------------------------------------------
__device__ __forceinline__ uint32_t smem_u32(const void* p) {
    uint32_t a;
    asm("{ .reg .u64 t; cvta.to.shared.u64 t, %1; cvt.u32.u64 %0, t; }" : "=r"(a) : "l"(p));
    return a;
}
__device__ __forceinline__ void cp_async16(float* dst, const float* src) {
    asm volatile("cp.async.cg.shared.global [%0], [%1], 16;"
                 :: "r"(smem_u32(dst)), "l"(src));
}
__device__ __forceinline__ void cp_async4(float* dst, const float* src) {
    asm volatile("cp.async.ca.shared.global [%0], [%1], 4;"
                 :: "r"(smem_u32(dst)), "l"(src));
}
#define CP_COMMIT() asm volatile("cp.async.commit_group;" ::: "memory")
#define CP_WAIT0()  asm volatile("cp.async.wait_group 0;" ::: "memory")

__device__ __forceinline__ uint32_t f2tf32(float f) {
    uint32_t u;
    asm("cvt.rna.tf32.f32 %0, %1;" : "=r"(u) : "f"(f));
    return u;
}
__device__ __forceinline__ void mma_tf32(float c[4], const uint32_t a[4],
                                         uint32_t b0, uint32_t b1) {
    asm("mma.sync.aligned.m16n8k8.row.col.f32.tf32.tf32.f32 "
        "{%0,%1,%2,%3}, {%4,%5,%6,%7}, {%8,%9}, {%0,%1,%2,%3};"
        : "+f"(c[0]), "+f"(c[1]), "+f"(c[2]), "+f"(c[3])
        : "r"(a[0]), "r"(a[1]), "r"(a[2]), "r"(a[3]), "r"(b0), "r"(b1));
}
__device__ __forceinline__ void red_add_v4(float4* a, float4 v) {
    asm volatile("red.global.add.v4.f32 [%0], {%1,%2,%3,%4};"
                 :: "l"(a), "f"(v.x), "f"(v.y), "f"(v.z), "f"(v.w) : "memory");
}

#define SA 132

// ---------------- Bperm: cp.async raw bits into permuted slots ---------------
//   l = (n&7)*4 + (k&3); re = ((n>>3)&3)*2 + ((k>>2)&1)
//   dest = (ng*16 + kc)*256 + (re>>2)*128 + l*4 + (re&3)
__device__ __forceinline__ void cp_Bperm_async(float* Bp, const float* __restrict__ w,
                                               int tid) {
    for (int idx = tid; idx < 16384; idx += 512) {
        const int k = idx >> 7;
        const int n = idx & 127;
        const int re = ((n >> 3) & 3) * 2 + ((k >> 2) & 1);
        const int dest = (((n >> 5) * 16 + (k >> 3)) << 8) + ((re >> 2) << 7) +
                         (((n & 7) * 4 + (k & 3)) << 2) + (re & 3);
        cp_async4(Bp + dest, w + idx);
    }
}
// in-smem convert raw f32 bits -> tf32 bits (identical rounding to before)
__device__ __forceinline__ void cvt_Bperm(float* Bp, int tid) {
    uint32_t* Bpu = (uint32_t*)Bp;
    for (int i = tid; i < 16384; i += 512)
        Bpu[i] = f2tf32(Bp[i]);
}
// legacy direct-load variants (used by encoder; amortized over many tiles)
__device__ __forceinline__ void load_Bperm(uint32_t* Bpu, const float* __restrict__ w,
                                           int tid, int nthreads) {
    for (int idx = tid; idx < 16384; idx += nthreads) {
        const int k = idx >> 7;
        const int n = idx & 127;
        const int re = ((n >> 3) & 3) * 2 + ((k >> 2) & 1);
        const int dest = (((n >> 5) * 16 + (k >> 3)) << 8) + ((re >> 2) << 7) +
                         (((n & 7) * 4 + (k & 3)) << 2) + (re & 3);
        Bpu[dest] = f2tf32(w[idx]);
    }
}
__device__ __forceinline__ void load_Bperm8(uint32_t* Bpu, const float* __restrict__ w,
                                            int tid, int nthreads) {
    for (int idx = tid; idx < 1024; idx += nthreads) {
        const int k = idx >> 7;          // 0..7
        const int n = idx & 127;
        const int ng = n >> 5;
        const int l  = (n & 7) * 4 + (k & 3);
        const int re = ((n >> 3) & 3) * 2 + (k >> 2);
        const int dest = (ng << 8) + ((re >> 2) << 7) + (l << 2) + (re & 3);
        Bpu[dest] = f2tf32(w[idx]);
    }
}

// 128 rows x 128 cols, 16B chunks, clamped rows -> A (raw f32)
__device__ __forceinline__ void cp_rows_async(float* A, const float* __restrict__ src,
                                              int n0, int n_nodes, int tid) {
    for (int i = tid; i < 4096; i += 512) {
        const int r = i >> 5, q = i & 31;
        int idx = n0 + r; if (idx >= n_nodes) idx = n_nodes - 1;
        cp_async16(A + r * SA + q * 4, src + (size_t)idx * H_DIM + q * 4);
    }
}

// ---------------- shared 16-kc double-buffered mma pass ----------------------
__device__ __forceinline__ void mma_tile_16kc(float cfr[2][4][4],
                                              const uint32_t* __restrict__ Au,
                                              const uint32_t* __restrict__ Bpu,
                                              int rm, int warp_n, int lane,
                                              int tg, int tq) {
    uint32_t abuf[2][2][4];
    uint32_t bbuf[2][8];

    auto load_frags = [&](int kc, int s) {
        const int k0 = kc * 8;
#pragma unroll
        for (int mt = 0; mt < 2; mt++) {
            const int rr = rm + mt * 16;
            abuf[s][mt][0] = Au[(rr + tg) * SA + k0 + tq];
            abuf[s][mt][1] = Au[(rr + tg + 8) * SA + k0 + tq];
            abuf[s][mt][2] = Au[(rr + tg) * SA + k0 + tq + 4];
            abuf[s][mt][3] = Au[(rr + tg + 8) * SA + k0 + tq + 4];
        }
        const uint32_t base = (uint32_t)((warp_n * 16 + kc) << 8);
        const uint4 q0 = *(const uint4*)(Bpu + base + (lane << 2));
        const uint4 q1 = *(const uint4*)(Bpu + base + 128 + (lane << 2));
        bbuf[s][0] = q0.x; bbuf[s][1] = q0.y; bbuf[s][2] = q0.z; bbuf[s][3] = q0.w;
        bbuf[s][4] = q1.x; bbuf[s][5] = q1.y; bbuf[s][6] = q1.z; bbuf[s][7] = q1.w;
    };

    load_frags(0, 0);
#pragma unroll
    for (int kc = 0; kc < 16; kc++) {
        const int cur = kc & 1, nxt = cur ^ 1;
        if (kc < 15) load_frags(kc + 1, nxt);
#pragma unroll
        for (int nt = 0; nt < 4; nt++) {
            mma_tf32(cfr[0][nt], abuf[cur][0], bbuf[cur][nt * 2], bbuf[cur][nt * 2 + 1]);
            mma_tf32(cfr[1][nt], abuf[cur][1], bbuf[cur][nt * 2], bbuf[cur][nt * 2 + 1]);
        }
    }
}

// ---------------- fused tensor encoder (lane + agent), 512 threads -----------
#define ENC_TILE_NODES 6
#define ENC5_SMEM_FLOATS (16896 + 16384 + 1024 + 1920 + 128 + 128)
#define ENC5_SMEM_BYTES  (ENC5_SMEM_FLOATS * 4)

__global__ void __launch_bounds__(512, 1)
enc_both_kernel(const float* __restrict__ lane_x,
                const float* __restrict__ lw1, const float* __restrict__ lb1,
                const float* __restrict__ lw2, const float* __restrict__ lb2,
                const float* __restrict__ ax,
                const float* __restrict__ aw1, const float* __restrict__ ab1,
                const float* __restrict__ aw2, const float* __restrict__ ab2,
                float* __restrict__ ms_l, float* __restrict__ ms_a)
{
    extern __shared__ float smem[];
    float* A     = smem;               // tf32 x' -> tf32 h -> f32 Dbuf
    float* Bperm = A + 16896;          // w2 permuted (16 kc)
    float* Bp1   = Bperm + 16384;      // w1 permuted (1 kc)
    float* xs    = Bp1 + 1024;         // 2 x 960
    float* b1s   = xs + 1920;
    float* b2s   = b1s + 128;

    uint32_t* Au   = (uint32_t*)A;
    uint32_t* Bpu  = (uint32_t*)Bperm;
    uint32_t* Bp1u = (uint32_t*)Bp1;

    const bool is_agent = blockIdx.x < AGENT_CTAS;
    const float* x_in = is_agent ? ax  : lane_x;
    const float* w1   = is_agent ? aw1 : lw1;
    const float* b1   = is_agent ? ab1 : lb1;
    const float* w2   = is_agent ? aw2 : lw2;
    const float* b2   = is_agent ? ab2 : lb2;
    float* ms_out     = is_agent ? ms_a : ms_l;
    const int n_nodes = is_agent ? N_AGENT : N_LANE;
    const int n_tiles = (n_nodes + ENC_TILE_NODES - 1) / ENC_TILE_NODES;
    const int cta0    = is_agent ? blockIdx.x : blockIdx.x - AGENT_CTAS;
    const int ncta    = is_agent ? AGENT_CTAS : TOTAL_CTAS - AGENT_CTAS;

    const int tid  = threadIdx.x;      // 0..511
    const int wid  = tid >> 5;         // 0..15
    const int lane = tid & 31;
    const int tg = lane >> 2;
    const int tq = lane & 3;
    const int warp_m = wid & 3;
    const int warp_n = wid >> 2;
    const int rm = warp_m * 32;

    load_Bperm(Bpu, w2, tid, 512);
    load_Bperm8(Bp1u, w1, tid, 512);
    if (tid < H_DIM) { b1s[tid] = b1[tid]; b2s[tid] = b2[tid]; }

    auto prefetch = [&](int tile, int buf) {
        const int node0 = tile * ENC_TILE_NODES;
        for (int i = tid; i < 240; i += 512) {
            int j = i / 40;
            int nd = node0 + j; if (nd >= n_nodes) nd = n_nodes - 1;
            cp_async16(xs + buf * 960 + i * 4,
                       x_in + (size_t)nd * 160 + (i - j * 40) * 4);
        }
    };

    int buf = 0;
    if (cta0 < n_tiles) { prefetch(cta0, 0); }
    CP_COMMIT();
    __syncthreads();                   // Bperm/Bp1/biases visible

    for (int tile = cta0; tile < n_tiles; tile += ncta) {
        const int node0 = tile * ENC_TILE_NODES;

        CP_WAIT0();
        __syncthreads();
        const float* xc = xs + buf * 960;

        {
            int ntile = tile + ncta;
            if (ntile < n_tiles) prefetch(ntile, buf ^ 1);
            CP_COMMIT();
        }

        // ---- build A = tf32(x') [120 rows x 8 k], ref-subtract folded ----
        for (int idx = tid; idx < 960; idx += 512) {
            const int r = idx >> 3, k = idx & 7;
            const int j = r / 20;
            const int t = r - j * 20;
            float val = xc[j * 160 + t * 8 + k];
            if (k < 2) val -= xc[j * 160 + 152 + k];
            Au[r * SA + k] = f2tf32(val);
        }
        __syncthreads();

        // ---- stage 1 mma: pre1 = x' @ w1 (single kc-step) ----
        float cfr[2][4][4];
#pragma unroll
        for (int mt = 0; mt < 2; mt++)
#pragma unroll
            for (int nt = 0; nt < 4; nt++)
#pragma unroll
                for (int q = 0; q < 4; q++) cfr[mt][nt][q] = 0.f;
        {
            uint32_t afr[2][4];
#pragma unroll
            for (int mt = 0; mt < 2; mt++) {
                const int rr = rm + mt * 16;
                afr[mt][0] = Au[(rr + tg) * SA + tq];
                afr[mt][1] = Au[(rr + tg + 8) * SA + tq];
                afr[mt][2] = Au[(rr + tg) * SA + tq + 4];
                afr[mt][3] = Au[(rr + tg + 8) * SA + tq + 4];
            }
            const uint32_t base = (uint32_t)(warp_n << 8);
            const uint4 q0 = *(const uint4*)(Bp1u + base + (lane << 2));
            const uint4 q1 = *(const uint4*)(Bp1u + base + 128 + (lane << 2));
#pragma unroll
            for (int mt = 0; mt < 2; mt++) {
                mma_tf32(cfr[mt][0], afr[mt], q0.x, q0.y);
                mma_tf32(cfr[mt][1], afr[mt], q0.z, q0.w);
                mma_tf32(cfr[mt][2], afr[mt], q1.x, q1.y);
                mma_tf32(cfr[mt][3], afr[mt], q1.z, q1.w);
            }
        }
        __syncthreads();   // all stage-1 A reads done before h overwrites A

        // ---- h = tf32(relu(pre1 + b1)) -> A ----
#pragma unroll
        for (int mt = 0; mt < 2; mt++) {
            const int rr = rm + mt * 16 + tg;
#pragma unroll
            for (int nt = 0; nt < 4; nt++) {
                const int cc = warp_n * 32 + nt * 8 + 2 * tq;
                Au[rr * SA + cc]     = f2tf32(fmaxf(cfr[mt][nt][0] + b1s[cc], 0.f));
                Au[rr * SA + cc + 1] = f2tf32(fmaxf(cfr[mt][nt][1] + b1s[cc + 1], 0.f));
                Au[(rr + 8) * SA + cc]     = f2tf32(fmaxf(cfr[mt][nt][2] + b1s[cc], 0.f));
                Au[(rr + 8) * SA + cc + 1] = f2tf32(fmaxf(cfr[mt][nt][3] + b1s[cc + 1], 0.f));
            }
        }
        __syncthreads();

        // ---- stage 2 mma: D = h @ w2 ----
#pragma unroll
        for (int mt = 0; mt < 2; mt++)
#pragma unroll
            for (int nt = 0; nt < 4; nt++)
#pragma unroll
                for (int q = 0; q < 4; q++) cfr[mt][nt][q] = 0.f;

        mma_tile_16kc(cfr, Au, Bpu, rm, warp_n, lane, tg, tq);
        __syncthreads();   // all A reads done; A memory becomes Dbuf

        // ---- store C frags to Dbuf (skip unused rows >= 120) ----
#pragma unroll
        for (int mt = 0; mt < 2; mt++) {
            const int rr = rm + mt * 16 + tg;
#pragma unroll
            for (int nt = 0; nt < 4; nt++) {
                const int cc = warp_n * 32 + nt * 8 + 2 * tq;
                if (rr < 120)
                    *(float2*)(A + rr * SA + cc) =
                        make_float2(cfr[mt][nt][0], cfr[mt][nt][1]);
                if (rr + 8 < 120)
                    *(float2*)(A + (rr + 8) * SA + cc) =
                        make_float2(cfr[mt][nt][2], cfr[mt][nt][3]);
            }
        }
        __syncthreads();

        // ---- per-node max + bias + relu -> ms ----
        for (int task = tid; task < ENC_TILE_NODES * H_DIM; task += 512) {
            const int j = task >> 7, cc = task & 127;
            const int nd = node0 + j;
            if (nd < n_nodes) {
                float m = -3.4e38f;
                const float* dp = A + (j * 20) * SA + cc;
#pragma unroll
                for (int r = 0; r < 20; r++) m = fmaxf(m, dp[r * SA]);
                ms_out[(size_t)nd * H_DIM + cc] = fmaxf(m + b2s[cc], 0.f);
            }
        }
        __syncthreads();
        buf ^= 1;
    }
}

// ---------------- fused tensor MLP (lane + agent), cp.async loads ------------
#define MLP2_SMEM_FLOATS (16896 + 16384 + 128)
#define MLP2_SMEM_BYTES  (MLP2_SMEM_FLOATS * 4)

__global__ void __launch_bounds__(512, 1)
mlp_both_kernel(const float* __restrict__ inL, const float* __restrict__ wL,
                const float* __restrict__ bL, float* __restrict__ outL,
                const float* __restrict__ inA, const float* __restrict__ wA,
                const float* __restrict__ bA, float* __restrict__ outA)
{
    extern __shared__ float smem[];
    float* A     = smem;
    float* Bperm = A + 16896;
    float* bs    = Bperm + 16384;
    uint32_t* Au  = (uint32_t*)A;
    uint32_t* Bpu = (uint32_t*)Bperm;

    const bool is_agent = blockIdx.x >= LANE_BLKS;
    const float* in_feat = is_agent ? inA : inL;
    const float* w       = is_agent ? wA : wL;
    const float* b       = is_agent ? bA : bL;
    float* out           = is_agent ? outA : outL;
    const int n_nodes    = is_agent ? N_AGENT : N_LANE;
    const int n0 = (is_agent ? (blockIdx.x - LANE_BLKS) : blockIdx.x) * 128;

    const int tid  = threadIdx.x;
    const int wid  = tid >> 5;
    const int lane = tid & 31;
    const int tg = lane >> 2;
    const int tq = lane & 3;
    const int warp_m = wid & 3;
    const int warp_n = wid >> 2;
    const int rm = warp_m * 32;

    cp_Bperm_async(Bperm, w, tid);
    cp_rows_async(A, in_feat, n0, n_nodes, tid);
    if (tid < H_DIM) bs[tid] = b[tid];
    CP_COMMIT(); CP_WAIT0();
    __syncthreads();

    cvt_Bperm(Bperm, tid);
    for (int i = tid; i < 16384; i += 512) {
        const int r = i >> 7, c = i & 127;
        Au[r * SA + c] = f2tf32(A[r * SA + c]);
    }
    __syncthreads();

    float cfr[2][4][4];
#pragma unroll
    for (int mt = 0; mt < 2; mt++)
#pragma unroll
        for (int nt = 0; nt < 4; nt++)
#pragma unroll
            for (int q = 0; q < 4; q++) cfr[mt][nt][q] = 0.f;

    mma_tile_16kc(cfr, Au, Bpu, rm, warp_n, lane, tg, tq);

#pragma unroll
    for (int mt = 0; mt < 2; mt++) {
        const int rr = rm + mt * 16 + tg;
#pragma unroll
        for (int nt = 0; nt < 4; nt++) {
            const int cc = warp_n * 32 + nt * 8 + 2 * tq;
            const float2 bv = make_float2(bs[cc], bs[cc + 1]);
            const int nd0 = n0 + rr;
            if (nd0 < n_nodes)
                *(float2*)(out + (size_t)nd0 * H_DIM + cc) =
                    make_float2(fmaxf(cfr[mt][nt][0] + bv.x, 0.f),
                                fmaxf(cfr[mt][nt][1] + bv.y, 0.f));
            const int nd1 = nd0 + 8;
            if (nd1 < n_nodes)
                *(float2*)(out + (size_t)nd1 * H_DIM + cc) =
                    make_float2(fmaxf(cfr[mt][nt][2] + bv.x, 0.f),
                                fmaxf(cfr[mt][nt][3] + bv.y, 0.f));
        }
    }
}

// ---------------- fused tensor GNN (cp.async loads; zeroes agg/deg) ----------
#define GNN2_SMEM_FLOATS (16896 + 16384 + 128 + 128 + 128)
#define GNN2_SMEM_BYTES  (GNN2_SMEM_FLOATS * 4)

__device__ __forceinline__ void gnn_body(
    const float* __restrict__ node_in, float* __restrict__ agg,
    float* __restrict__ deg,
    const float* __restrict__ w1, const float* __restrict__ b1,
    const float* __restrict__ w2, const float* __restrict__ b2,
    float* __restrict__ out, int n_nodes, int n0)
{
    extern __shared__ float smem[];
    float* A     = smem;
    float* Bperm = A + 16896;
    float* bs1   = Bperm + 16384;
    float* bs2   = bs1 + 128;
    float* degs  = bs2 + 128;
    uint32_t* Au  = (uint32_t*)A;
    uint32_t* Bpu = (uint32_t*)Bperm;

    const int tid  = threadIdx.x;
    const int wid  = tid >> 5;
    const int lane = tid & 31;
    const int tg = lane >> 2;
    const int tq = lane & 3;
    const int warp_m = wid & 3;
    const int warp_n = wid >> 2;
    const int rm = warp_m * 32;

    // phase 0: cp.async w1[0:128] -> Bperm, node rows -> A, biases
    cp_Bperm_async(Bperm, w1, tid);
    cp_rows_async(A, node_in, n0, n_nodes, tid);
    if (tid < H_DIM) { bs1[tid] = b1[tid]; bs2[tid] = b2[tid]; }
    CP_COMMIT(); CP_WAIT0();
    __syncthreads();

    cvt_Bperm(Bperm, tid);
    for (int i = tid; i < 16384; i += 512) {
        const int r = i >> 7, c = i & 127;
        Au[r * SA + c] = f2tf32(A[r * SA + c]);
    }
    __syncthreads();

    float cfr[2][4][4];
#pragma unroll
    for (int mt = 0; mt < 2; mt++)
#pragma unroll
        for (int nt = 0; nt < 4; nt++)
#pragma unroll
            for (int q = 0; q < 4; q++) cfr[mt][nt][q] = 0.f;

    mma_tile_16kc(cfr, Au, Bpu, rm, warp_n, lane, tg, tq);
    __syncthreads();

    // phase 2: cp.async w1[128:256] -> Bperm, agg rows -> A (raw), deg -> smem
    cp_Bperm_async(Bperm, w1 + 128 * H_DIM, tid);
    cp_rows_async(A, agg, n0, n_nodes, tid);
    if (tid < 128) degs[tid] = (n0 + tid < n_nodes) ? deg[n0 + tid] : 1.f;
    CP_COMMIT(); CP_WAIT0();
    __syncthreads();

    cvt_Bperm(Bperm, tid);
    for (int i = tid; i < 16384; i += 512) {
        const int r = i >> 7, c = i & 127;
        const float invd = 1.0f / fmaxf(degs[r], 1.0f);
        Au[r * SA + c] = f2tf32(A[r * SA + c] * invd);
        const int idx = n0 + r;
        if (idx < n_nodes) agg[(size_t)idx * H_DIM + c] = 0.f;   // restore invariant
    }
    if (tid < 128 && n0 + tid < n_nodes) deg[n0 + tid] = 0.f;    // degs smem copy retained
    __syncthreads();

    mma_tile_16kc(cfr, Au, Bpu, rm, warp_n, lane, tg, tq);
    __syncthreads();

    // phase 4: cp.async w2 -> Bperm (overlaps h-write); h = relu(cfr+b1) -> A
    cp_Bperm_async(Bperm, w2, tid);
    CP_COMMIT();
#pragma unroll
    for (int mt = 0; mt < 2; mt++) {
        const int rr = rm + mt * 16 + tg;
#pragma unroll
        for (int nt = 0; nt < 4; nt++) {
            const int cc = warp_n * 32 + nt * 8 + 2 * tq;
            Au[rr * SA + cc]     = f2tf32(fmaxf(cfr[mt][nt][0] + bs1[cc], 0.f));
            Au[rr * SA + cc + 1] = f2tf32(fmaxf(cfr[mt][nt][1] + bs1[cc + 1], 0.f));
            Au[(rr + 8) * SA + cc]     = f2tf32(fmaxf(cfr[mt][nt][2] + bs1[cc], 0.f));
            Au[(rr + 8) * SA + cc + 1] = f2tf32(fmaxf(cfr[mt][nt][3] + bs1[cc + 1], 0.f));
        }
    }
    CP_WAIT0();
    __syncthreads();
    cvt_Bperm(Bperm, tid);
    __syncthreads();

    // phase 6: layer 2 mma
#pragma unroll
    for (int mt = 0; mt < 2; mt++)
#pragma unroll
        for (int nt = 0; nt < 4; nt++)
#pragma unroll
            for (int q = 0; q < 4; q++) cfr[mt][nt][q] = 0.f;

    mma_tile_16kc(cfr, Au, Bpu, rm, warp_n, lane, tg, tq);

    // epilogue: out = node + relu(cfr + b2)
#pragma unroll
    for (int mt = 0; mt < 2; mt++) {
        const int rr = rm + mt * 16 + tg;
#pragma unroll
        for (int nt = 0; nt < 4; nt++) {
            const int cc = warp_n * 32 + nt * 8 + 2 * tq;
            const float2 bv = make_float2(bs2[cc], bs2[cc + 1]);
            const int nd0 = n0 + rr;
            if (nd0 < n_nodes) {
                const float2 nv = *(const float2*)(node_in + (size_t)nd0 * H_DIM + cc);
                *(float2*)(out + (size_t)nd0 * H_DIM + cc) =
                    make_float2(nv.x + fmaxf(cfr[mt][nt][0] + bv.x, 0.f),
                                nv.y + fmaxf(cfr[mt][nt][1] + bv.y, 0.f));
            }
            const int nd1 = nd0 + 8;
            if (nd1 < n_nodes) {
                const float2 nv = *(const float2*)(node_in + (size_t)nd1 * H_DIM + cc);
                *(float2*)(out + (size_t)nd1 * H_DIM + cc) =
                    make_float2(nv.x + fmaxf(cfr[mt][nt][2] + bv.x, 0.f),
                                nv.y + fmaxf(cfr[mt][nt][3] + bv.y, 0.f));
            }
        }
    }
}

__global__ void __launch_bounds__(512, 1)
gnn_both_kernel(const float* __restrict__ lane_in, float* __restrict__ lane_agg,
                float* __restrict__ deg_l,
                const float* __restrict__ ll_w1, const float* __restrict__ ll_b1,
                const float* __restrict__ ll_w2, const float* __restrict__ ll_b2,
                float* __restrict__ lane_out,
                const float* __restrict__ agent_in, float* __restrict__ agent_agg,
                float* __restrict__ deg_a,
                const float* __restrict__ aa_w1, const float* __restrict__ aa_b1,
                const float* __restrict__ aa_w2, const float* __restrict__ aa_b2,
                float* __restrict__ agent_out)
{
    if (blockIdx.x < LANE_BLKS) {
        gnn_body(lane_in, lane_agg, deg_l, ll_w1, ll_b1, ll_w2, ll_b2,
                 lane_out, N_LANE, blockIdx.x * 128);
    } else {
        gnn_body(agent_in, agent_agg, deg_a, aa_w1, aa_b1, aa_w2, aa_b2,
                 agent_out, N_AGENT, (blockIdx.x - LANE_BLKS) * 128);
    }
}

__global__ void __launch_bounds__(512, 1)
gnn_la_kernel(const float* __restrict__ node_in, float* __restrict__ agg,
              float* __restrict__ deg,
              const float* __restrict__ w1, const float* __restrict__ b1,
              const float* __restrict__ w2, const float* __restrict__ b2,
              float* __restrict__ out)
{
    gnn_body(node_in, agg, deg, w1, b1, w2, b2, out, N_AGENT,
             blockIdx.x * 128);
}

// ---------------- fused edge scatter (LL + AA), grid-stride + idx prefetch ---
__global__ void scatter_both_kernel(const int* __restrict__ e_ll,
                                    const int* __restrict__ e_aa,
                                    const float* __restrict__ lane_feat,
                                    float* __restrict__ lane_agg,
                                    float* __restrict__ deg_l,
                                    const float* __restrict__ agent_feat,
                                    float* __restrict__ agent_agg,
                                    float* __restrict__ deg_a)
{
    const int nwarps = (gridDim.x * blockDim.x) >> 5;
    const int lane = threadIdx.x & 31;
    int e = (blockIdx.x * blockDim.x + threadIdx.x) >> 5;
    const int total = E_LL + E_AA;
    if (e >= total) return;

    auto load_idx = [&](int ei, int& s, int& d) {
        if (ei < E_LL) { s = e_ll[ei]; d = e_ll[E_LL + ei]; }
        else           { s = e_aa[ei - E_LL]; d = e_aa[E_AA + ei - E_LL]; }
    };

    int s, d;
    load_idx(e, s, d);
    while (e < total) {
        const int en = e + nwarps;
        int s2 = 0, d2 = 0;
        if (en < total) load_idx(en, s2, d2);

        const bool is_ll = e < E_LL;
        const float* feat = is_ll ? lane_feat : agent_feat;
        float* agg = is_ll ? lane_agg : agent_agg;
        float* deg = is_ll ? deg_l : deg_a;

        const float4 v = ((const float4*)(feat + (size_t)s * H_DIM))[lane];
        red_add_v4(((float4*)(agg + (size_t)d * H_DIM)) + lane, v);
        if (lane == 0) atomicAdd(deg + d, 1.0f);

        e = en; s = s2; d = d2;
    }
}

__global__ void scatter_la_kernel(const int* __restrict__ e_la,
                                  const float* __restrict__ feat,
                                  float* __restrict__ agg,
                                  float* __restrict__ deg)
{
    const int nwarps = (gridDim.x * blockDim.x) >> 5;
    const int lane = threadIdx.x & 31;
    int e = (blockIdx.x * blockDim.x + threadIdx.x) >> 5;
    if (e >= E_LA) return;

    int s = e_la[e], d = e_la[E_LA + e];
    while (e < E_LA) {
        const int en = e + nwarps;
        int s2 = 0, d2 = 0;
        if (en < E_LA) { s2 = e_la[en]; d2 = e_la[E_LA + en]; }

        const float4 v = ((const float4*)(feat + (size_t)s * H_DIM))[lane];
        red_add_v4(((float4*)(agg + (size_t)d * H_DIM)) + lane, v);
        if (lane == 0) atomicAdd(deg + d, 1.0f);

        e = en; s = s2; d = d2;
    }
}

// ---------------- launch -----------------------------------------------------
extern "C" void kernel_launch(void* const* d_in, const int* in_sizes, int n_in,
                              void* d_out, int out_size)
{
    const float* lane_points   = (const float*)d_in[0];
    const float* agent_history = (const float*)d_in[1];
    const int* e_ll = (const int*)d_in[2];
    const int* e_aa = (const int*)d_in[3];
    const int* e_la = (const int*)d_in[4];
    const float* lw1 = (const float*)d_in[5];
    const float* lb1 = (const float*)d_in[6];
    const float* lw2 = (const float*)d_in[7];
    const float* lb2 = (const float*)d_in[8];
    const float* lw3 = (const float*)d_in[9];
    const float* lb3 = (const float*)d_in[10];
    const float* aw1 = (const float*)d_in[11];
    const float* ab1 = (const float*)d_in[12];
    const float* aw2 = (const float*)d_in[13];
    const float* ab2 = (const float*)d_in[14];
    const float* aw3 = (const float*)d_in[15];
    const float* ab3 = (const float*)d_in[16];
    const float* ll_w1 = (const float*)d_in[17];
    const float* ll_b1 = (const float*)d_in[18];
    const float* ll_w2 = (const float*)d_in[19];
    const float* ll_b2 = (const float*)d_in[20];
    const float* aa_w1 = (const float*)d_in[21];
    const float* aa_b1 = (const float*)d_in[22];
    const float* aa_w2 = (const float*)d_in[23];
    const float* aa_b2 = (const float*)d_in[24];
    const float* la_w1 = (const float*)d_in[25];
    const float* la_b1 = (const float*)d_in[26];
    const float* la_w2 = (const float*)d_in[27];
    const float* la_b2 = (const float*)d_in[28];

    float* out = (float*)d_out;
    float* lane_out  = out;
    float* agent_out = out + (size_t)N_LANE * H_DIM;

    float *p_lane_enc, *p_agent_enc, *p_lane_agg, *p_agent_agg;
    float *p_ms_l, *p_ms_a, *p_deg_l, *p_deg_a;
    cudaGetSymbolAddress((void**)&p_lane_enc,  g_lane_enc);
    cudaGetSymbolAddress((void**)&p_agent_enc, g_agent_enc);
    cudaGetSymbolAddress((void**)&p_lane_agg,  g_lane_agg);
    cudaGetSymbolAddress((void**)&p_agent_agg, g_agent_agg);
    cudaGetSymbolAddress((void**)&p_ms_l,      g_ms_l);
    cudaGetSymbolAddress((void**)&p_ms_a,      g_ms_a);
    cudaGetSymbolAddress((void**)&p_deg_l,     g_deg_l);
    cudaGetSymbolAddress((void**)&p_deg_a,     g_deg_a);

    cudaFuncSetAttribute(enc_both_kernel, cudaFuncAttributeMaxDynamicSharedMemorySize, ENC5_SMEM_BYTES);
    cudaFuncSetAttribute(mlp_both_kernel, cudaFuncAttributeMaxDynamicSharedMemorySize, MLP2_SMEM_BYTES);
    cudaFuncSetAttribute(gnn_both_kernel, cudaFuncAttributeMaxDynamicSharedMemorySize, GNN2_SMEM_BYTES);
    cudaFuncSetAttribute(gnn_la_kernel,   cudaFuncAttributeMaxDynamicSharedMemorySize, GNN2_SMEM_BYTES);

    // NOTE: no zero kernel — agg/deg buffers are zero-init device globals and
    // each GNN pass re-zeroes what it consumed (invariant holds every call).

    // 1. fused encoders (agent CTAs 0..24, lane CTAs 25..147)
    enc_both_kernel<<<TOTAL_CTAS, 512, ENC5_SMEM_BYTES>>>(
        lane_points, lw1, lb1, lw2, lb2,
        agent_history, aw1, ab1, aw2, ab2, p_ms_l, p_ms_a);

    // 2. fused stage-3 MLPs
    mlp_both_kernel<<<LANE_BLKS + AGENT_BLKS, 512, MLP2_SMEM_BYTES>>>(
        p_ms_l, lw3, lb3, p_lane_enc,
        p_ms_a, aw3, ab3, p_agent_enc);

    // 3. fused LL + AA scatter (grid-stride, index-prefetch)
    scatter_both_kernel<<<SCAT_BLKS, 256>>>(
        e_ll, e_aa, p_lane_enc, p_lane_agg, p_deg_l,
        p_agent_enc, p_agent_agg, p_deg_a);

    // 4. fused LL + AA GNN (both halves zero their agg/deg after reading)
    gnn_both_kernel<<<LANE_BLKS + AGENT_BLKS, 512, GNN2_SMEM_BYTES>>>(
        p_lane_enc, p_lane_agg, p_deg_l, ll_w1, ll_b1, ll_w2, ll_b2, lane_out,
        p_agent_enc, p_agent_agg, p_deg_a, aa_w1, aa_b1, aa_w2, aa_b2, agent_out);

    // 5. LA scatter (source = updated lane; agent agg/deg zeroed by step 4)
    scatter_la_kernel<<<SCAT_BLKS, 256>>>(e_la, lane_out, p_agent_agg, p_deg_a);

    // 6. LA GNN (in-place on agent_out; zeroes agent agg/deg for next call)
    gnn_la_kernel<<<AGENT_BLKS, 512, GNN2_SMEM_BYTES>>>(
        agent_out, p_agent_agg, p_deg_a, la_w1, la_b1, la_w2, la_b2, agent_out);
}